// round 2
// baseline (speedup 1.0000x reference)
#include <cuda_runtime.h>
#include <cuda_bf16.h>
#include <math.h>

#define BN 8
#define CC 128
#define HH 56
#define WW 56
#define HWSZ (HH*WW)

// ---------------- scratch (static __device__, no allocations) ----------------
__device__ __align__(16) float g_h1[BN*CC*HWSZ];              // conv1 output
__device__ __align__(16) float g_off[BN*18*HWSZ];             // offset conv output
__device__ __align__(16) float g_samp[BN*9*CC*HWSZ];          // bilinear-sampled tensor
__device__ __align__(16) float g_h2[BN*CC*HWSZ];              // dcn output
__device__ __align__(16) float g_h3[BN*CC*HWSZ];              // conv2 output
__device__ float g_mean[CC];
__device__ float g_rstd[CC];
__device__ __align__(16) float g_w1p[CC*256*12];   // conv1 weights padded 9->12
__device__ __align__(16) float g_w2p[CC*CC*12];    // conv2 weights padded
__device__ __align__(16) float g_dcnwt[CC*1152];   // dcn weights transposed [o][k*128+c]

// ---------------- weight prep ----------------
__global__ void prep_pad(const float* __restrict__ w, float* __restrict__ wp, int n) {
    int i = blockIdx.x*256 + threadIdx.x;
    if (i < n) {
        #pragma unroll
        for (int k = 0; k < 9; k++) wp[i*12+k] = w[i*9+k];
        wp[i*12+9] = 0.f; wp[i*12+10] = 0.f; wp[i*12+11] = 0.f;
    }
}

__global__ void prep_dcn(const float* __restrict__ w) {
    int i = blockIdx.x*256 + threadIdx.x;           // over 128*1152
    if (i < CC*1152) {
        int o = i / 1152;
        int kc = i % 1152;
        int k = kc >> 7;
        int c = kc & 127;
        g_dcnwt[i] = w[(o*CC + c)*9 + k];
    }
}

// ---------------- generic 3x3 conv, Co=128, thread tile 4w x 8co ----------------
template<int CIN, bool CONCAT>
__global__ __launch_bounds__(128) void conv3x3(
    const float* __restrict__ inA, const float* __restrict__ inB,
    const float* __restrict__ wp, const float* __restrict__ bias,
    float* __restrict__ out)
{
    const int tx = threadIdx.x;            // 0..13 -> w groups of 4
    const int ty = threadIdx.y;            // 0..7  -> co groups of 8
    const int h  = blockIdx.y;
    const int b  = blockIdx.z;
    const int co0 = blockIdx.x*64 + ty*8;
    const int wb  = tx*4;

    float acc[8][4];
    #pragma unroll
    for (int i = 0; i < 8; i++)
        #pragma unroll
        for (int j = 0; j < 4; j++) acc[i][j] = 0.f;

    for (int ci = 0; ci < CIN; ci++) {
        const float* ip;
        if (CONCAT)
            ip = (ci < 128) ? (inA + (size_t)(b*128 + ci)*HWSZ)
                            : (inB + (size_t)(b*128 + ci - 128)*HWSZ);
        else
            ip = inA + (size_t)(b*CIN + ci)*HWSZ;

        float r[3][6];
        #pragma unroll
        for (int dy = 0; dy < 3; dy++) {
            int yy = h + dy - 1;
            bool yok = ((unsigned)yy < HH);
            const float* rp = ip + yy*WW;
            #pragma unroll
            for (int dx = 0; dx < 6; dx++) {
                int xx = wb + dx - 1;
                r[dy][dx] = (yok && (unsigned)xx < WW) ? __ldg(rp + xx) : 0.f;
            }
        }

        #pragma unroll
        for (int i = 0; i < 8; i++) {
            const float4* wq = (const float4*)(wp + (size_t)((co0+i)*CIN + ci)*12);
            float4 wa = __ldg(wq);
            float4 wb4 = __ldg(wq+1);
            float4 wc = __ldg(wq+2);
            #pragma unroll
            for (int j = 0; j < 4; j++) {
                acc[i][j] += r[0][j]*wa.x + r[0][j+1]*wa.y + r[0][j+2]*wa.z
                           + r[1][j]*wa.w + r[1][j+1]*wb4.x + r[1][j+2]*wb4.y
                           + r[2][j]*wb4.z + r[2][j+1]*wb4.w + r[2][j+2]*wc.x;
            }
        }
    }

    #pragma unroll
    for (int i = 0; i < 8; i++) {
        float bi = bias[co0+i];
        float4* op = (float4*)(out + (size_t)(b*128 + co0 + i)*HWSZ + h*WW + wb);
        *op = make_float4(acc[i][0]+bi, acc[i][1]+bi, acc[i][2]+bi, acc[i][3]+bi);
    }
}

// ---------------- offset conv: 128 -> 18, 3x3 ----------------
__global__ __launch_bounds__(64) void offconv(
    const float* __restrict__ w, const float* __restrict__ bias)
{
    int x = threadIdx.x;
    if (x >= WW) return;
    int h = blockIdx.x;
    int b = blockIdx.y;

    float acc[18];
    #pragma unroll
    for (int co = 0; co < 18; co++) acc[co] = bias[co];

    for (int ci = 0; ci < 128; ci++) {
        const float* ip = g_h1 + (size_t)(b*128 + ci)*HWSZ;
        float r[9];
        #pragma unroll
        for (int dy = 0; dy < 3; dy++) {
            int yy = h + dy - 1;
            bool yok = ((unsigned)yy < HH);
            #pragma unroll
            for (int dx = 0; dx < 3; dx++) {
                int xx = x + dx - 1;
                r[dy*3+dx] = (yok && (unsigned)xx < WW) ? __ldg(ip + yy*WW + xx) : 0.f;
            }
        }
        #pragma unroll
        for (int co = 0; co < 18; co++) {
            const float* wq = w + (size_t)(co*128 + ci)*9;
            float s = 0.f;
            #pragma unroll
            for (int k = 0; k < 9; k++) s += r[k]*__ldg(wq+k);
            acc[co] += s;
        }
    }
    #pragma unroll
    for (int co = 0; co < 18; co++)
        g_off[(size_t)(b*18 + co)*HWSZ + h*WW + x] = acc[co];
}

// ---------------- bilinear sampling: build g_samp[b][k][c][hw] ----------------
__global__ __launch_bounds__(64) void sample_k()
{
    int x = threadIdx.x;
    if (x >= WW) return;
    int h = blockIdx.x;
    int b = blockIdx.y;
    int k = blockIdx.z;
    int hw = h*WW + x;

    float oy = g_off[(size_t)(b*18 + 2*k    )*HWSZ + hw];
    float ox = g_off[(size_t)(b*18 + 2*k + 1)*HWSZ + hw];
    float py = (float)(h + k/3 - 1) + oy;
    float px = (float)(x + k%3 - 1) + ox;

    float y0f = floorf(py), x0f = floorf(px);
    float wy1 = py - y0f, wy0 = 1.f - wy1;
    float wx1 = px - x0f, wx0 = 1.f - wx1;
    int y0 = (int)y0f, x0i = (int)x0f;

    int idx[4]; float wv[4];
    int ys[4] = {y0, y0, y0+1, y0+1};
    int xs[4] = {x0i, x0i+1, x0i, x0i+1};
    float ws[4] = {wy0*wx0, wy0*wx1, wy1*wx0, wy1*wx1};
    #pragma unroll
    for (int t = 0; t < 4; t++) {
        bool v = (ys[t] >= 0) && (ys[t] <= HH-1) && (xs[t] >= 0) && (xs[t] <= WW-1);
        int iy = min(max(ys[t], 0), HH-1);
        int ix = min(max(xs[t], 0), WW-1);
        idx[t] = iy*WW + ix;
        wv[t]  = v ? ws[t] : 0.f;
    }

    const float* xb = g_h1 + (size_t)b*128*HWSZ;
    float* ob = g_samp + (size_t)(b*1152 + k*128)*HWSZ + hw;
    for (int c = 0; c < 128; c++) {
        const float* xp = xb + (size_t)c*HWSZ;
        float v = wv[0]*__ldg(xp+idx[0]) + wv[1]*__ldg(xp+idx[1])
                + wv[2]*__ldg(xp+idx[2]) + wv[3]*__ldg(xp+idx[3]);
        ob[(size_t)c*HWSZ] = v;
    }
}

// ---------------- dcn contraction: out[b,o,hw] = sum_kc samp[b,kc,hw]*Wt[o,kc] ----------------
__global__ __launch_bounds__(224) void dcn_k(const float* __restrict__ bias)
{
    const int tx = threadIdx.x;          // 0..27 -> hw groups of 4
    const int ty = threadIdx.y;          // 0..7  -> co groups of 8
    const int b  = blockIdx.z;
    const int co0 = blockIdx.y*64 + ty*8;
    const int hw0 = (blockIdx.x*28 + tx)*4;

    float acc[8][4];
    #pragma unroll
    for (int i = 0; i < 8; i++)
        #pragma unroll
        for (int j = 0; j < 4; j++) acc[i][j] = 0.f;

    const float* sbase = g_samp + (size_t)b*1152*HWSZ + hw0;
    for (int kc = 0; kc < 1152; kc += 4) {
        float4 s0 = *(const float4*)(sbase + (size_t)(kc+0)*HWSZ);
        float4 s1 = *(const float4*)(sbase + (size_t)(kc+1)*HWSZ);
        float4 s2 = *(const float4*)(sbase + (size_t)(kc+2)*HWSZ);
        float4 s3 = *(const float4*)(sbase + (size_t)(kc+3)*HWSZ);
        #pragma unroll
        for (int i = 0; i < 8; i++) {
            float4 wv = *(const float4*)(g_dcnwt + (size_t)(co0+i)*1152 + kc);
            acc[i][0] += s0.x*wv.x + s1.x*wv.y + s2.x*wv.z + s3.x*wv.w;
            acc[i][1] += s0.y*wv.x + s1.y*wv.y + s2.y*wv.z + s3.y*wv.w;
            acc[i][2] += s0.z*wv.x + s1.z*wv.y + s2.z*wv.z + s3.z*wv.w;
            acc[i][3] += s0.w*wv.x + s1.w*wv.y + s2.w*wv.z + s3.w*wv.w;
        }
    }

    #pragma unroll
    for (int i = 0; i < 8; i++) {
        float bi = bias[co0+i];
        float4* op = (float4*)(g_h2 + (size_t)(b*128 + co0 + i)*HWSZ + hw0);
        *op = make_float4(acc[i][0]+bi, acc[i][1]+bi, acc[i][2]+bi, acc[i][3]+bi);
    }
}

// ---------------- BN stats (per channel over B,H,W) ----------------
__global__ __launch_bounds__(256) void bnstats()
{
    int c = blockIdx.x;
    int tid = threadIdx.x;
    float s = 0.f, s2 = 0.f;
    for (int i = tid; i < BN*HWSZ; i += 256) {
        int b = i / HWSZ, hw = i % HWSZ;
        float v = g_h3[(size_t)(b*128 + c)*HWSZ + hw];
        s += v; s2 += v*v;
    }
    __shared__ float sh[256], sh2[256];
    sh[tid] = s; sh2[tid] = s2;
    __syncthreads();
    for (int o = 128; o > 0; o >>= 1) {
        if (tid < o) { sh[tid] += sh[tid+o]; sh2[tid] += sh2[tid+o]; }
        __syncthreads();
    }
    if (tid == 0) {
        float n = (float)(BN*HWSZ);
        float mean = sh[0]/n;
        float var  = sh2[0]/n - mean*mean;
        g_mean[c] = mean;
        g_rstd[c] = rsqrtf(var + 1e-5f);
    }
}

// ---------------- BN + exact GELU, write h into d_out ----------------
__global__ __launch_bounds__(256) void bngelu(
    const float* __restrict__ gamma, const float* __restrict__ beta,
    float* __restrict__ out)
{
    int i = blockIdx.x*256 + threadIdx.x;
    if (i >= BN*CC*HWSZ) return;
    int c = (i / HWSZ) & 127;
    float v = g_h3[i];
    v = (v - g_mean[c]) * g_rstd[c] * gamma[c] + beta[c];
    out[i] = 0.5f * v * (1.f + erff(v * 0.70710678118654752440f));
}

// ---------------- mask conv: 128 -> 1, 3x3, reads h from d_out ----------------
__global__ __launch_bounds__(64) void maskconv(
    const float* __restrict__ hsrc, const float* __restrict__ w,
    const float* __restrict__ bias, float* __restrict__ out)
{
    int x = threadIdx.x;
    if (x >= WW) return;
    int h = blockIdx.x;
    int b = blockIdx.y;
    float acc = bias[0];
    for (int ci = 0; ci < 128; ci++) {
        const float* ip = hsrc + (size_t)(b*128 + ci)*HWSZ;
        const float* wq = w + (size_t)ci*9;
        #pragma unroll
        for (int dy = 0; dy < 3; dy++) {
            int yy = h + dy - 1;
            if ((unsigned)yy >= HH) continue;
            #pragma unroll
            for (int dx = 0; dx < 3; dx++) {
                int xx = x + dx - 1;
                if ((unsigned)xx < WW)
                    acc += __ldg(ip + yy*WW + xx) * __ldg(wq + dy*3 + dx);
            }
        }
    }
    out[(size_t)b*HWSZ + h*WW + x] = acc;
}

// ---------------- launch ----------------
extern "C" void kernel_launch(void* const* d_in, const int* in_sizes, int n_in,
                              void* d_out, int out_size)
{
    const float* x       = (const float*)d_in[0];
    const float* y       = (const float*)d_in[1];
    const float* conv_w  = (const float*)d_in[2];
    const float* conv_b  = (const float*)d_in[3];
    const float* off_w   = (const float*)d_in[4];
    const float* off_b   = (const float*)d_in[5];
    const float* dcn_w   = (const float*)d_in[6];
    const float* dcn_b   = (const float*)d_in[7];
    const float* conv2_w = (const float*)d_in[8];
    const float* conv2_b = (const float*)d_in[9];
    const float* bn_g    = (const float*)d_in[10];
    const float* bn_b    = (const float*)d_in[11];
    const float* mask_w  = (const float*)d_in[12];
    const float* mask_b  = (const float*)d_in[13];
    float* out = (float*)d_out;

    float *p_h1, *p_h3, *p_w1p, *p_w2p, *p_h2;
    cudaGetSymbolAddress((void**)&p_h1,  g_h1);
    cudaGetSymbolAddress((void**)&p_h2,  g_h2);
    cudaGetSymbolAddress((void**)&p_h3,  g_h3);
    cudaGetSymbolAddress((void**)&p_w1p, g_w1p);
    cudaGetSymbolAddress((void**)&p_w2p, g_w2p);

    // weight prep
    prep_pad<<<(128*256 + 255)/256, 256>>>(conv_w, p_w1p, 128*256);
    prep_pad<<<(128*128 + 255)/256, 256>>>(conv2_w, p_w2p, 128*128);
    prep_dcn<<<(CC*1152 + 255)/256, 256>>>(dcn_w);

    dim3 cblk(14, 8);
    dim3 cgrd(2, HH, BN);

    // conv1: concat(x,y) 256 -> 128
    conv3x3<256, true><<<cgrd, cblk>>>(x, y, p_w1p, conv_b, p_h1);

    // offset conv 128 -> 18
    offconv<<<dim3(HH, BN), 64>>>(off_w, off_b);

    // bilinear sampling
    sample_k<<<dim3(HH, BN, 9), 64>>>();

    // dcn contraction
    dcn_k<<<dim3(28, 2, BN), dim3(28, 8)>>>(dcn_b);

    // conv2: 128 -> 128
    conv3x3<128, false><<<cgrd, cblk>>>(p_h2, nullptr, p_w2p, conv2_b, p_h3);

    // batch norm stats + apply + GELU -> d_out (h region)
    bnstats<<<CC, 256>>>();
    bngelu<<<(BN*CC*HWSZ + 255)/256, 256>>>(bn_g, bn_b, out);

    // mask conv 128 -> 1 -> d_out (mask region)
    maskconv<<<dim3(HH, BN), 64>>>(out, mask_w, mask_b, out + (size_t)BN*CC*HWSZ);

    (void)in_sizes; (void)n_in; (void)out_size;
}

// round 3
// speedup vs baseline: 1.3843x; 1.3843x over previous
#include <cuda_runtime.h>
#include <cuda_bf16.h>
#include <math.h>

#define BN 8
#define CC 128
#define HH 56
#define WW 56
#define HWSZ (HH*WW)

// ---------------- scratch (static __device__, no allocations) ----------------
__device__ __align__(16) float g_h1[BN*CC*HWSZ];
__device__ __align__(16) float g_off[BN*18*HWSZ];
__device__ __align__(16) float g_offp[4*BN*18*HWSZ];      // split-ci partials
__device__ __align__(16) float g_samp[BN*9*CC*HWSZ];
__device__ __align__(16) float g_h2[BN*CC*HWSZ];
__device__ __align__(16) float g_h3[BN*CC*HWSZ];
__device__ __align__(16) float g_maskp[4*BN*HWSZ];
__device__ float g_mean[CC];
__device__ float g_rstd[CC];
__device__ __align__(16) float g_w1p[CC*256*12];          // conv1 w padded 9->12
__device__ __align__(16) float g_w2p[CC*CC*12];           // conv2 w padded
__device__ __align__(16) float g_dcnwt[CC*1152];          // dcn w transposed [o][k*128+c]
__device__ __align__(16) float g_offwt[CC*18*12];         // off w [ci][co][12]
__device__ __align__(16) float g_maskwt[CC*12];           // mask w [ci][12]

// ---------------- weight prep ----------------
__global__ void prep_pad(const float* __restrict__ w, float* __restrict__ wp, int n) {
    int i = blockIdx.x*256 + threadIdx.x;
    if (i < n) {
        #pragma unroll
        for (int k = 0; k < 9; k++) wp[i*12+k] = w[i*9+k];
        wp[i*12+9] = 0.f; wp[i*12+10] = 0.f; wp[i*12+11] = 0.f;
    }
}

__global__ void prep_dcn(const float* __restrict__ w) {
    int i = blockIdx.x*256 + threadIdx.x;
    if (i < CC*1152) {
        int o = i / 1152;
        int kc = i % 1152;
        int k = kc >> 7;
        int c = kc & 127;
        g_dcnwt[i] = w[(o*CC + c)*9 + k];
    }
}

__global__ void prep_offw(const float* __restrict__ w) {   // [18,128,9] -> [ci][co][12]
    int i = blockIdx.x*256 + threadIdx.x;                   // over 128*18
    if (i < CC*18) {
        int ci = i / 18, co = i % 18;
        #pragma unroll
        for (int k = 0; k < 9; k++) g_offwt[i*12+k] = w[(co*CC+ci)*9+k];
        g_offwt[i*12+9]=0.f; g_offwt[i*12+10]=0.f; g_offwt[i*12+11]=0.f;
    }
}

__global__ void prep_maskw(const float* __restrict__ w) {  // [1,128,9] -> [ci][12]
    int i = blockIdx.x*256 + threadIdx.x;
    if (i < CC) {
        #pragma unroll
        for (int k = 0; k < 9; k++) g_maskwt[i*12+k] = w[i*9+k];
        g_maskwt[i*12+9]=0.f; g_maskwt[i*12+10]=0.f; g_maskwt[i*12+11]=0.f;
    }
}

// ---------------- 3x3 conv: thread tile 4co x 2h x 4w ----------------
template<int CIN, bool CONCAT>
__global__ __launch_bounds__(112, 6) void conv3x3(
    const float* __restrict__ inA, const float* __restrict__ inB,
    const float* __restrict__ wp, const float* __restrict__ bias,
    float* __restrict__ out)
{
    const int tx = threadIdx.x;            // 0..13 -> w groups of 4
    const int ty = threadIdx.y;            // 0..7  -> co groups of 4
    const int h0 = blockIdx.y*2;
    const int b  = blockIdx.z;
    const int co0 = blockIdx.x*32 + ty*4;
    const int wb  = tx*4;

    float acc[4][2][4];
    #pragma unroll
    for (int i = 0; i < 4; i++)
        #pragma unroll
        for (int hh = 0; hh < 2; hh++)
            #pragma unroll
            for (int j = 0; j < 4; j++) acc[i][hh][j] = 0.f;

    for (int ci = 0; ci < CIN; ci++) {
        const float* ip;
        if (CONCAT)
            ip = (ci < 128) ? (inA + (size_t)(b*128 + ci)*HWSZ)
                            : (inB + (size_t)(b*128 + ci - 128)*HWSZ);
        else
            ip = inA + (size_t)(b*CIN + ci)*HWSZ;

        float r[4][6];
        #pragma unroll
        for (int dy = 0; dy < 4; dy++) {
            int yy = h0 + dy - 1;
            bool yok = ((unsigned)yy < HH);
            const float* rp = ip + yy*WW;
            #pragma unroll
            for (int dx = 0; dx < 6; dx++) {
                int xx = wb + dx - 1;
                r[dy][dx] = (yok && (unsigned)xx < WW) ? __ldg(rp + xx) : 0.f;
            }
        }

        #pragma unroll
        for (int i = 0; i < 4; i++) {
            const float4* wq = (const float4*)(wp + (size_t)((co0+i)*CIN + ci)*12);
            float4 wa  = __ldg(wq);
            float4 wb4 = __ldg(wq+1);
            float4 wc  = __ldg(wq+2);
            #pragma unroll
            for (int hh = 0; hh < 2; hh++) {
                #pragma unroll
                for (int j = 0; j < 4; j++) {
                    acc[i][hh][j] += r[hh+0][j]*wa.x + r[hh+0][j+1]*wa.y + r[hh+0][j+2]*wa.z
                                   + r[hh+1][j]*wa.w + r[hh+1][j+1]*wb4.x + r[hh+1][j+2]*wb4.y
                                   + r[hh+2][j]*wb4.z + r[hh+2][j+1]*wb4.w + r[hh+2][j+2]*wc.x;
                }
            }
        }
    }

    #pragma unroll
    for (int i = 0; i < 4; i++) {
        float bi = bias[co0+i];
        #pragma unroll
        for (int hh = 0; hh < 2; hh++) {
            float4* op = (float4*)(out + (size_t)(b*128 + co0 + i)*HWSZ + (h0+hh)*WW + wb);
            *op = make_float4(acc[i][hh][0]+bi, acc[i][hh][1]+bi, acc[i][hh][2]+bi, acc[i][hh][3]+bi);
        }
    }
}

// ---------------- offset conv: split-ci partials ----------------
__global__ __launch_bounds__(224) void offconv_part()
{
    int x  = threadIdx.x;                  // 0..55
    int h  = blockIdx.x*4 + threadIdx.y;   // 4 rows per block
    int b  = blockIdx.y;
    int ch = blockIdx.z;                   // ci chunk 0..3
    int ci0 = ch*32;
    int hw = h*WW + x;

    float acc[18];
    #pragma unroll
    for (int co = 0; co < 18; co++) acc[co] = 0.f;

    for (int ci = 0; ci < 32; ci++) {
        const float* ip = g_h1 + (size_t)(b*128 + ci0 + ci)*HWSZ;
        float r[9];
        #pragma unroll
        for (int dy = 0; dy < 3; dy++) {
            int yy = h + dy - 1;
            bool yok = ((unsigned)yy < HH);
            #pragma unroll
            for (int dx = 0; dx < 3; dx++) {
                int xx = x + dx - 1;
                r[dy*3+dx] = (yok && (unsigned)xx < WW) ? __ldg(ip + yy*WW + xx) : 0.f;
            }
        }
        const float4* wbase = (const float4*)(g_offwt + (size_t)(ci0+ci)*18*12);
        #pragma unroll
        for (int co = 0; co < 18; co++) {
            float4 wa  = __ldg(wbase + co*3);
            float4 wb4 = __ldg(wbase + co*3 + 1);
            float4 wc  = __ldg(wbase + co*3 + 2);
            acc[co] += r[0]*wa.x + r[1]*wa.y + r[2]*wa.z
                     + r[3]*wa.w + r[4]*wb4.x + r[5]*wb4.y
                     + r[6]*wb4.z + r[7]*wb4.w + r[8]*wc.x;
        }
    }
    #pragma unroll
    for (int co = 0; co < 18; co++)
        g_offp[(size_t)((ch*BN + b)*18 + co)*HWSZ + hw] = acc[co];
}

__global__ __launch_bounds__(256) void offconv_reduce(const float* __restrict__ bias)
{
    int i = blockIdx.x*256 + threadIdx.x;
    if (i >= BN*18*HWSZ) return;
    int co = (i / HWSZ) % 18;
    float v = bias[co];
    #pragma unroll
    for (int ch = 0; ch < 4; ch++)
        v += g_offp[(size_t)ch*BN*18*HWSZ + i];
    g_off[i] = v;
}

// ---------------- bilinear sampling ----------------
__global__ __launch_bounds__(64) void sample_k()
{
    int x = threadIdx.x;
    if (x >= WW) return;
    int h = blockIdx.x;
    int b = blockIdx.y;
    int k = blockIdx.z;
    int hw = h*WW + x;

    float oy = g_off[(size_t)(b*18 + 2*k    )*HWSZ + hw];
    float ox = g_off[(size_t)(b*18 + 2*k + 1)*HWSZ + hw];
    float py = (float)(h + k/3 - 1) + oy;
    float px = (float)(x + k%3 - 1) + ox;

    float y0f = floorf(py), x0f = floorf(px);
    float wy1 = py - y0f, wy0 = 1.f - wy1;
    float wx1 = px - x0f, wx0 = 1.f - wx1;
    int y0 = (int)y0f, x0i = (int)x0f;

    int idx[4]; float wv[4];
    int ys[4] = {y0, y0, y0+1, y0+1};
    int xs[4] = {x0i, x0i+1, x0i, x0i+1};
    float ws[4] = {wy0*wx0, wy0*wx1, wy1*wx0, wy1*wx1};
    #pragma unroll
    for (int t = 0; t < 4; t++) {
        bool v = (ys[t] >= 0) && (ys[t] <= HH-1) && (xs[t] >= 0) && (xs[t] <= WW-1);
        int iy = min(max(ys[t], 0), HH-1);
        int ix = min(max(xs[t], 0), WW-1);
        idx[t] = iy*WW + ix;
        wv[t]  = v ? ws[t] : 0.f;
    }

    const float* xb = g_h1 + (size_t)b*128*HWSZ;
    float* ob = g_samp + (size_t)(b*1152 + k*128)*HWSZ + hw;
    for (int c = 0; c < 128; c++) {
        const float* xp = xb + (size_t)c*HWSZ;
        float v = wv[0]*__ldg(xp+idx[0]) + wv[1]*__ldg(xp+idx[1])
                + wv[2]*__ldg(xp+idx[2]) + wv[3]*__ldg(xp+idx[3]);
        ob[(size_t)c*HWSZ] = v;
    }
}

// ---------------- dcn contraction ----------------
__global__ __launch_bounds__(224) void dcn_k(const float* __restrict__ bias)
{
    const int tx = threadIdx.x;          // 0..27 -> hw groups of 4
    const int ty = threadIdx.y;          // 0..7  -> co groups of 8
    const int b  = blockIdx.z;
    const int co0 = blockIdx.y*64 + ty*8;
    const int hw0 = (blockIdx.x*28 + tx)*4;

    float acc[8][4];
    #pragma unroll
    for (int i = 0; i < 8; i++)
        #pragma unroll
        for (int j = 0; j < 4; j++) acc[i][j] = 0.f;

    const float* sbase = g_samp + (size_t)b*1152*HWSZ + hw0;
    for (int kc = 0; kc < 1152; kc += 4) {
        float4 s0 = *(const float4*)(sbase + (size_t)(kc+0)*HWSZ);
        float4 s1 = *(const float4*)(sbase + (size_t)(kc+1)*HWSZ);
        float4 s2 = *(const float4*)(sbase + (size_t)(kc+2)*HWSZ);
        float4 s3 = *(const float4*)(sbase + (size_t)(kc+3)*HWSZ);
        #pragma unroll
        for (int i = 0; i < 8; i++) {
            float4 wv = *(const float4*)(g_dcnwt + (size_t)(co0+i)*1152 + kc);
            acc[i][0] += s0.x*wv.x + s1.x*wv.y + s2.x*wv.z + s3.x*wv.w;
            acc[i][1] += s0.y*wv.x + s1.y*wv.y + s2.y*wv.z + s3.y*wv.w;
            acc[i][2] += s0.z*wv.x + s1.z*wv.y + s2.z*wv.z + s3.z*wv.w;
            acc[i][3] += s0.w*wv.x + s1.w*wv.y + s2.w*wv.z + s3.w*wv.w;
        }
    }

    #pragma unroll
    for (int i = 0; i < 8; i++) {
        float bi = bias[co0+i];
        float4* op = (float4*)(g_h2 + (size_t)(b*128 + co0 + i)*HWSZ + hw0);
        *op = make_float4(acc[i][0]+bi, acc[i][1]+bi, acc[i][2]+bi, acc[i][3]+bi);
    }
}

// ---------------- BN stats ----------------
__global__ __launch_bounds__(256) void bnstats()
{
    int c = blockIdx.x;
    int tid = threadIdx.x;
    float s = 0.f, s2 = 0.f;
    for (int i = tid; i < BN*HWSZ; i += 256) {
        int b = i / HWSZ, hw = i % HWSZ;
        float v = g_h3[(size_t)(b*128 + c)*HWSZ + hw];
        s += v; s2 += v*v;
    }
    __shared__ float sh[256], sh2[256];
    sh[tid] = s; sh2[tid] = s2;
    __syncthreads();
    for (int o = 128; o > 0; o >>= 1) {
        if (tid < o) { sh[tid] += sh[tid+o]; sh2[tid] += sh2[tid+o]; }
        __syncthreads();
    }
    if (tid == 0) {
        float n = (float)(BN*HWSZ);
        float mean = sh[0]/n;
        float var  = sh2[0]/n - mean*mean;
        g_mean[c] = mean;
        g_rstd[c] = rsqrtf(var + 1e-5f);
    }
}

// ---------------- BN + exact GELU -> d_out ----------------
__global__ __launch_bounds__(256) void bngelu(
    const float* __restrict__ gamma, const float* __restrict__ beta,
    float* __restrict__ out)
{
    int i = blockIdx.x*256 + threadIdx.x;
    if (i >= BN*CC*HWSZ) return;
    int c = (i / HWSZ) & 127;
    float v = g_h3[i];
    v = (v - g_mean[c]) * g_rstd[c] * gamma[c] + beta[c];
    out[i] = 0.5f * v * (1.f + erff(v * 0.70710678118654752440f));
}

// ---------------- mask conv: split-ci partials ----------------
__global__ __launch_bounds__(224) void maskconv_part(const float* __restrict__ hsrc)
{
    int x  = threadIdx.x;                  // 0..55
    int h  = blockIdx.x*4 + threadIdx.y;
    int b  = blockIdx.y;
    int ch = blockIdx.z;
    int ci0 = ch*32;
    int hw = h*WW + x;

    float acc = 0.f;
    for (int ci = 0; ci < 32; ci++) {
        const float* ip = hsrc + (size_t)(b*128 + ci0 + ci)*HWSZ;
        float r[9];
        #pragma unroll
        for (int dy = 0; dy < 3; dy++) {
            int yy = h + dy - 1;
            bool yok = ((unsigned)yy < HH);
            #pragma unroll
            for (int dx = 0; dx < 3; dx++) {
                int xx = x + dx - 1;
                r[dy*3+dx] = (yok && (unsigned)xx < WW) ? __ldg(ip + yy*WW + xx) : 0.f;
            }
        }
        const float4* wq = (const float4*)(g_maskwt + (size_t)(ci0+ci)*12);
        float4 wa  = __ldg(wq);
        float4 wb4 = __ldg(wq+1);
        float4 wc  = __ldg(wq+2);
        acc += r[0]*wa.x + r[1]*wa.y + r[2]*wa.z
             + r[3]*wa.w + r[4]*wb4.x + r[5]*wb4.y
             + r[6]*wb4.z + r[7]*wb4.w + r[8]*wc.x;
    }
    g_maskp[(size_t)(ch*BN + b)*HWSZ + hw] = acc;
}

__global__ __launch_bounds__(256) void maskconv_reduce(
    const float* __restrict__ bias, float* __restrict__ out)
{
    int i = blockIdx.x*256 + threadIdx.x;
    if (i >= BN*HWSZ) return;
    float v = bias[0];
    #pragma unroll
    for (int ch = 0; ch < 4; ch++)
        v += g_maskp[(size_t)ch*BN*HWSZ + i];
    out[i] = v;
}

// ---------------- launch ----------------
extern "C" void kernel_launch(void* const* d_in, const int* in_sizes, int n_in,
                              void* d_out, int out_size)
{
    const float* x       = (const float*)d_in[0];
    const float* y       = (const float*)d_in[1];
    const float* conv_w  = (const float*)d_in[2];
    const float* conv_b  = (const float*)d_in[3];
    const float* off_w   = (const float*)d_in[4];
    const float* off_b   = (const float*)d_in[5];
    const float* dcn_w   = (const float*)d_in[6];
    const float* dcn_b   = (const float*)d_in[7];
    const float* conv2_w = (const float*)d_in[8];
    const float* conv2_b = (const float*)d_in[9];
    const float* bn_g    = (const float*)d_in[10];
    const float* bn_b    = (const float*)d_in[11];
    const float* mask_w  = (const float*)d_in[12];
    const float* mask_b  = (const float*)d_in[13];
    float* out = (float*)d_out;

    float *p_h1, *p_h3, *p_w1p, *p_w2p, *p_h2;
    cudaGetSymbolAddress((void**)&p_h1,  g_h1);
    cudaGetSymbolAddress((void**)&p_h2,  g_h2);
    cudaGetSymbolAddress((void**)&p_h3,  g_h3);
    cudaGetSymbolAddress((void**)&p_w1p, g_w1p);
    cudaGetSymbolAddress((void**)&p_w2p, g_w2p);

    // weight prep
    prep_pad<<<(128*256 + 255)/256, 256>>>(conv_w, p_w1p, 128*256);
    prep_pad<<<(128*128 + 255)/256, 256>>>(conv2_w, p_w2p, 128*128);
    prep_dcn<<<(CC*1152 + 255)/256, 256>>>(dcn_w);
    prep_offw<<<(CC*18 + 255)/256, 256>>>(off_w);
    prep_maskw<<<1, 256>>>(mask_w);

    dim3 cblk(14, 8);
    dim3 cgrd(4, 28, BN);

    // conv1: concat(x,y) 256 -> 128
    conv3x3<256, true><<<cgrd, cblk>>>(x, y, p_w1p, conv_b, p_h1);

    // offset conv 128 -> 18 (split ci, then reduce)
    offconv_part<<<dim3(14, BN, 4), dim3(56, 4)>>>();
    offconv_reduce<<<(BN*18*HWSZ + 255)/256, 256>>>(off_b);

    // bilinear sampling
    sample_k<<<dim3(HH, BN, 9), 64>>>();

    // dcn contraction
    dcn_k<<<dim3(28, 2, BN), dim3(28, 8)>>>(dcn_b);

    // conv2: 128 -> 128
    conv3x3<128, false><<<cgrd, cblk>>>(p_h2, nullptr, p_w2p, conv2_b, p_h3);

    // batch norm stats + apply + GELU -> d_out
    bnstats<<<CC, 256>>>();
    bngelu<<<(BN*CC*HWSZ + 255)/256, 256>>>(bn_g, bn_b, out);

    // mask conv 128 -> 1 (split ci, then reduce) -> d_out tail
    maskconv_part<<<dim3(14, BN, 4), dim3(56, 4)>>>(out);
    maskconv_reduce<<<(BN*HWSZ + 255)/256, 256>>>(mask_b, out + (size_t)BN*CC*HWSZ);

    (void)in_sizes; (void)n_in; (void)out_size;
}

// round 5
// speedup vs baseline: 2.6153x; 1.8893x over previous
#include <cuda_runtime.h>
#include <cuda_bf16.h>
#include <math.h>
#include <stdint.h>

#define BN 8
#define CC 128
#define HH 56
#define WW 56
#define HWSZ (HH*WW)

// ---------------- scratch (static __device__, no allocations) ----------------
__device__ __align__(16) float g_h1[BN*CC*HWSZ];
__device__ __align__(16) float g_off[BN*18*HWSZ];
__device__ __align__(16) float g_offp[4*BN*18*HWSZ];
__device__ __align__(16) float g_samp[BN*9*CC*HWSZ];      // dcn B operand [b][k*128+c][hw]
__device__ __align__(16) float g_col[BN*2304*HWSZ];       // im2col scratch
__device__ __align__(16) float g_h2[BN*CC*HWSZ];
__device__ __align__(16) float g_h3[BN*CC*HWSZ];
__device__ __align__(16) float g_maskp[4*BN*HWSZ];
__device__ float g_mean[CC];
__device__ float g_rstd[CC];
// A operands: per k16-chunk, per m16-tile, per term(hi/lo): 32 lanes x 4 u32 fragment order
__device__ __align__(16) uint8_t g_w1g[144*8192];         // conv1 (K=2304 -> 144 k16)
__device__ __align__(16) uint8_t g_w2g[72*8192];          // conv2 (K=1152)
__device__ __align__(16) uint8_t g_wdg[72*8192];          // dcn
__device__ __align__(16) float g_offwt[CC*18*12];
__device__ __align__(16) float g_maskwt[CC*12];

__device__ __forceinline__ uint32_t smem_u32(const void* p) {
    uint32_t a;
    asm("{ .reg .u64 t; cvta.to.shared.u64 t, %1; cvt.u32.u64 %0, t; }" : "=r"(a) : "l"(p));
    return a;
}
__device__ __forceinline__ uint16_t bf16_bits(float x) {
    __nv_bfloat16 h = __float2bfloat16(x);
    uint16_t u; *(__nv_bfloat16*)&u = h; return u;
}
__device__ __forceinline__ float bf16_val(uint16_t u) {
    __nv_bfloat16 h; *(uint16_t*)&h = u; return __bfloat162float(h);
}

// ---------------- GEMM via mma.sync m16n8k16 bf16, 3-term split ----------------
// C[b, co=128, px0+0..63] = sum_K A[co,K]*Bsrc[b,K,px] + bias
__global__ __launch_bounds__(256) void gemm_mma(
    const float* __restrict__ Bsrc, const uint8_t* __restrict__ Ag,
    const float* __restrict__ bias, float* __restrict__ out, int nstages)  // K = nstages*32
{
    __shared__ uint16_t sB[2][32][72];       // [term][k][px], pad 64->72
    const int tid = threadIdx.x, lid = tid & 31, wid = tid >> 5;
    const int warpM = wid & 3, warpN = wid >> 2;
    const int b = blockIdx.y;
    const int px0 = blockIdx.x * 64;
    const int K = nstages * 32;

    const float* bb = Bsrc + (size_t)b * K * HWSZ + px0;

    float c[2][4][4];
    #pragma unroll
    for (int mt = 0; mt < 2; mt++)
        #pragma unroll
        for (int nt = 0; nt < 4; nt++)
            #pragma unroll
            for (int r = 0; r < 4; r++) c[mt][nt][r] = 0.f;

    // precompute ldmatrix lane addresses (k,n) pattern
    const int lmtx = lid >> 3, lrow = lid & 7;
    const int lk = ((lmtx & 1) << 3) + lrow;             // 0..15 within k16
    const int ln = warpN * 32 + ((lmtx >> 1) << 3);      // n offset (q adds 16)
    const uint32_t sbh = smem_u32(&sB[0][0][0]);
    const uint32_t sbl = smem_u32(&sB[1][0][0]);

    for (int stage = 0; stage < nstages; stage++) {
        if (stage) __syncthreads();
        // stage B: 32 k-rows x 64 px fp32 -> bf16 hi/lo planes
        #pragma unroll
        for (int r2 = 0; r2 < 2; r2++) {
            int f = tid + r2 * 256;          // 0..511
            int row = f >> 4, c4 = f & 15;
            float4 t = __ldg((const float4*)(bb + (size_t)(stage * 32 + row) * HWSZ + c4 * 4));
            uint16_t hx = bf16_bits(t.x), hy = bf16_bits(t.y), hz = bf16_bits(t.z), hw = bf16_bits(t.w);
            uint16_t lx = bf16_bits(t.x - bf16_val(hx));
            uint16_t ly = bf16_bits(t.y - bf16_val(hy));
            uint16_t lz = bf16_bits(t.z - bf16_val(hz));
            uint16_t lw = bf16_bits(t.w - bf16_val(hw));
            uint2 hp = make_uint2((uint32_t)hx | ((uint32_t)hy << 16), (uint32_t)hz | ((uint32_t)hw << 16));
            uint2 lp = make_uint2((uint32_t)lx | ((uint32_t)ly << 16), (uint32_t)lz | ((uint32_t)lw << 16));
            *(uint2*)&sB[0][row][c4 * 4] = hp;
            *(uint2*)&sB[1][row][c4 * 4] = lp;
        }
        __syncthreads();

        #pragma unroll
        for (int s = 0; s < 2; s++) {
            const int kk = stage * 2 + s;
            // A fragments from gmem (pre-shuffled): [kk][mt_g 8][term 2][lane][4 u32]
            uint4 ah[2], al[2];
            #pragma unroll
            for (int mt = 0; mt < 2; mt++) {
                const uint4* ap = (const uint4*)Ag + (size_t)((kk * 8 + warpM * 2 + mt) * 2) * 32 + lid;
                ah[mt] = __ldg(ap);
                al[mt] = __ldg(ap + 32);
            }
            // B fragments via ldmatrix.x4.trans
            uint32_t bh[2][4], bl[2][4];
            #pragma unroll
            for (int q = 0; q < 2; q++) {
                uint32_t off = (uint32_t)((s * 16 + lk) * 72 + ln + q * 16) * 2;
                asm volatile("ldmatrix.sync.aligned.m8n8.x4.trans.shared.b16 {%0,%1,%2,%3}, [%4];"
                    : "=r"(bh[q][0]), "=r"(bh[q][1]), "=r"(bh[q][2]), "=r"(bh[q][3]) : "r"(sbh + off));
                asm volatile("ldmatrix.sync.aligned.m8n8.x4.trans.shared.b16 {%0,%1,%2,%3}, [%4];"
                    : "=r"(bl[q][0]), "=r"(bl[q][1]), "=r"(bl[q][2]), "=r"(bl[q][3]) : "r"(sbl + off));
            }
            #pragma unroll
            for (int mt = 0; mt < 2; mt++) {
                #pragma unroll
                for (int q = 0; q < 2; q++) {
                    #pragma unroll
                    for (int h = 0; h < 2; h++) {
                        float* cc = c[mt][q * 2 + h];
                        #define MMA(AF, B0, B1) \
                            asm volatile("mma.sync.aligned.m16n8k16.row.col.f32.bf16.bf16.f32 " \
                                "{%0,%1,%2,%3}, {%4,%5,%6,%7}, {%8,%9}, {%0,%1,%2,%3};" \
                                : "+f"(cc[0]), "+f"(cc[1]), "+f"(cc[2]), "+f"(cc[3]) \
                                : "r"(AF.x), "r"(AF.y), "r"(AF.z), "r"(AF.w), "r"(B0), "r"(B1))
                        MMA(ah[mt], bh[q][h * 2], bh[q][h * 2 + 1]);
                        MMA(ah[mt], bl[q][h * 2], bl[q][h * 2 + 1]);
                        MMA(al[mt], bh[q][h * 2], bh[q][h * 2 + 1]);
                        #undef MMA
                    }
                }
            }
        }
    }

    // writeout
    #pragma unroll
    for (int mt = 0; mt < 2; mt++) {
        int row = warpM * 32 + mt * 16 + (lid >> 2);
        float bi0 = bias[row], bi8 = bias[row + 8];
        #pragma unroll
        for (int nt = 0; nt < 4; nt++) {
            int col = warpN * 32 + nt * 8 + (lid & 3) * 2;
            float* o0 = out + (size_t)(b * 128 + row) * HWSZ + px0 + col;
            *(float2*)o0 = make_float2(c[mt][nt][0] + bi0, c[mt][nt][1] + bi0);
            *(float2*)(o0 + 8 * HWSZ) = make_float2(c[mt][nt][2] + bi8, c[mt][nt][3] + bi8);
        }
    }
}

// ---------------- weight prep: per-lane fragment order, hi/lo split ----------------
// mode 0: conv, kg = tap*CIN+ci, w[co][ci][tap]   mode 1: dcn, kg = k*128+c, w[co][c][k]
__global__ void prep_wgemm(const float* __restrict__ w, uint8_t* __restrict__ dst, int CIN, int mode) {
    int K = CIN * 9;
    int i = blockIdx.x * 256 + threadIdx.x;
    if (i >= 128 * K) return;
    int co = i / K, kg = i % K;
    float v;
    if (mode == 0) { int tap = kg / CIN, ci = kg % CIN; v = w[((size_t)co * CIN + ci) * 9 + tap]; }
    else           { int k = kg >> 7,   c  = kg & 127;  v = w[((size_t)co * 128 + c) * 9 + k]; }
    uint16_t hb = bf16_bits(v);
    uint16_t lb = bf16_bits(v - bf16_val(hb));
    int kk = kg >> 4, kin = kg & 15;
    int mt = co >> 4, row = co & 15;
    int lane = (row & 7) * 4 + ((kin & 7) >> 1);
    int reg = (row >> 3) + ((kin >> 3) << 1);
    int half = kin & 1;
    uint16_t* d16 = (uint16_t*)dst;
    size_t base = ((size_t)(kk * 8 + mt) * 2) * 128 + lane * 4 + reg;
    d16[base * 2 + half] = hb;                       // term hi
    d16[(base + 128) * 2 + half] = lb;               // term lo
}

__global__ void prep_offw(const float* __restrict__ w) {
    int i = blockIdx.x*256 + threadIdx.x;
    if (i < CC*18) {
        int ci = i / 18, co = i % 18;
        #pragma unroll
        for (int k = 0; k < 9; k++) g_offwt[i*12+k] = w[(co*CC+ci)*9+k];
        g_offwt[i*12+9]=0.f; g_offwt[i*12+10]=0.f; g_offwt[i*12+11]=0.f;
    }
}
__global__ void prep_maskw(const float* __restrict__ w) {
    int i = blockIdx.x*256 + threadIdx.x;
    if (i < CC) {
        #pragma unroll
        for (int k = 0; k < 9; k++) g_maskwt[i*12+k] = w[i*9+k];
        g_maskwt[i*12+9]=0.f; g_maskwt[i*12+10]=0.f; g_maskwt[i*12+11]=0.f;
    }
}

// ---------------- im2col ----------------
__global__ __launch_bounds__(256) void im2col(
    const float* __restrict__ A, const float* __restrict__ B2,
    float* __restrict__ col, int CIN)
{
    int kc = blockIdx.x;
    int b  = blockIdx.y;
    int K  = CIN * 9;
    int tap = kc / CIN, ci = kc % CIN;
    int dy = tap / 3 - 1, dx = tap % 3 - 1;
    const float* src;
    if (ci < 128) src = A + (size_t)(b * 128 + ci) * HWSZ;
    else          src = B2 + (size_t)(b * 128 + ci - 128) * HWSZ;
    float* dst = col + ((size_t)b * K + kc) * HWSZ;
    for (int i = threadIdx.x; i < HWSZ; i += 256) {
        int y = i / WW, x = i - y * WW;
        int yy = y + dy, xx = x + dx;
        float v = ((unsigned)yy < HH && (unsigned)xx < WW) ? __ldg(src + yy * WW + xx) : 0.f;
        dst[i] = v;
    }
}

// ---------------- offset conv (split-ci) ----------------
__global__ __launch_bounds__(224) void offconv_part()
{
    int x  = threadIdx.x;
    int h  = blockIdx.x*4 + threadIdx.y;
    int b  = blockIdx.y;
    int ch = blockIdx.z;
    int ci0 = ch*32;
    int hw = h*WW + x;

    float acc[18];
    #pragma unroll
    for (int co = 0; co < 18; co++) acc[co] = 0.f;

    for (int ci = 0; ci < 32; ci++) {
        const float* ip = g_h1 + (size_t)(b*128 + ci0 + ci)*HWSZ;
        float r[9];
        #pragma unroll
        for (int dy = 0; dy < 3; dy++) {
            int yy = h + dy - 1;
            bool yok = ((unsigned)yy < HH);
            #pragma unroll
            for (int dx = 0; dx < 3; dx++) {
                int xx = x + dx - 1;
                r[dy*3+dx] = (yok && (unsigned)xx < WW) ? __ldg(ip + yy*WW + xx) : 0.f;
            }
        }
        const float4* wbase = (const float4*)(g_offwt + (size_t)(ci0+ci)*18*12);
        #pragma unroll
        for (int co = 0; co < 18; co++) {
            float4 wa  = __ldg(wbase + co*3);
            float4 wb4 = __ldg(wbase + co*3 + 1);
            float4 wc  = __ldg(wbase + co*3 + 2);
            acc[co] += r[0]*wa.x + r[1]*wa.y + r[2]*wa.z
                     + r[3]*wa.w + r[4]*wb4.x + r[5]*wb4.y
                     + r[6]*wb4.z + r[7]*wb4.w + r[8]*wc.x;
        }
    }
    #pragma unroll
    for (int co = 0; co < 18; co++)
        g_offp[(size_t)((ch*BN + b)*18 + co)*HWSZ + hw] = acc[co];
}

__global__ __launch_bounds__(256) void offconv_reduce(const float* __restrict__ bias)
{
    int i = blockIdx.x*256 + threadIdx.x;
    if (i >= BN*18*HWSZ) return;
    int co = (i / HWSZ) % 18;
    float v = bias[co];
    #pragma unroll
    for (int ch = 0; ch < 4; ch++)
        v += g_offp[(size_t)ch*BN*18*HWSZ + i];
    g_off[i] = v;
}

// ---------------- bilinear sampling -> g_samp[b][k*128+c][hw] ----------------
__global__ __launch_bounds__(64) void sample_k()
{
    int x = threadIdx.x;
    if (x >= WW) return;
    int h = blockIdx.x;
    int b = blockIdx.y;
    int k = blockIdx.z;
    int hw = h*WW + x;

    float oy = g_off[(size_t)(b*18 + 2*k    )*HWSZ + hw];
    float ox = g_off[(size_t)(b*18 + 2*k + 1)*HWSZ + hw];
    float py = (float)(h + k/3 - 1) + oy;
    float px = (float)(x + k%3 - 1) + ox;

    float y0f = floorf(py), x0f = floorf(px);
    float wy1 = py - y0f, wy0 = 1.f - wy1;
    float wx1 = px - x0f, wx0 = 1.f - wx1;
    int y0 = (int)y0f, x0i = (int)x0f;

    int idx[4]; float wv[4];
    int ys[4] = {y0, y0, y0+1, y0+1};
    int xs[4] = {x0i, x0i+1, x0i, x0i+1};
    float ws[4] = {wy0*wx0, wy0*wx1, wy1*wx0, wy1*wx1};
    #pragma unroll
    for (int t = 0; t < 4; t++) {
        bool v = (ys[t] >= 0) && (ys[t] <= HH-1) && (xs[t] >= 0) && (xs[t] <= WW-1);
        int iy = min(max(ys[t], 0), HH-1);
        int ix = min(max(xs[t], 0), WW-1);
        idx[t] = iy*WW + ix;
        wv[t]  = v ? ws[t] : 0.f;
    }

    const float* xb = g_h1 + (size_t)b*128*HWSZ;
    float* ob = g_samp + (size_t)(b*1152 + k*128)*HWSZ + hw;
    for (int c = 0; c < 128; c++) {
        const float* xp = xb + (size_t)c*HWSZ;
        float v = wv[0]*__ldg(xp+idx[0]) + wv[1]*__ldg(xp+idx[1])
                + wv[2]*__ldg(xp+idx[2]) + wv[3]*__ldg(xp+idx[3]);
        ob[(size_t)c*HWSZ] = v;
    }
}

// ---------------- BN stats ----------------
__global__ __launch_bounds__(256) void bnstats()
{
    int c = blockIdx.x;
    int tid = threadIdx.x;
    float s = 0.f, s2 = 0.f;
    for (int i = tid; i < BN*HWSZ; i += 256) {
        int b = i / HWSZ, hw = i % HWSZ;
        float v = g_h3[(size_t)(b*128 + c)*HWSZ + hw];
        s += v; s2 += v*v;
    }
    __shared__ float sh[256], sh2[256];
    sh[tid] = s; sh2[tid] = s2;
    __syncthreads();
    for (int o = 128; o > 0; o >>= 1) {
        if (tid < o) { sh[tid] += sh[tid+o]; sh2[tid] += sh2[tid+o]; }
        __syncthreads();
    }
    if (tid == 0) {
        float n = (float)(BN*HWSZ);
        float mean = sh[0]/n;
        float var  = sh2[0]/n - mean*mean;
        g_mean[c] = mean;
        g_rstd[c] = rsqrtf(var + 1e-5f);
    }
}

__global__ __launch_bounds__(256) void bngelu(
    const float* __restrict__ gamma, const float* __restrict__ beta,
    float* __restrict__ out)
{
    int i = blockIdx.x*256 + threadIdx.x;
    if (i >= BN*CC*HWSZ) return;
    int c = (i / HWSZ) & 127;
    float v = g_h3[i];
    v = (v - g_mean[c]) * g_rstd[c] * gamma[c] + beta[c];
    out[i] = 0.5f * v * (1.f + erff(v * 0.70710678118654752440f));
}

// ---------------- mask conv (split-ci) ----------------
__global__ __launch_bounds__(224) void maskconv_part(const float* __restrict__ hsrc)
{
    int x  = threadIdx.x;
    int h  = blockIdx.x*4 + threadIdx.y;
    int b  = blockIdx.y;
    int ch = blockIdx.z;
    int ci0 = ch*32;
    int hw = h*WW + x;

    float acc = 0.f;
    for (int ci = 0; ci < 32; ci++) {
        const float* ip = hsrc + (size_t)(b*128 + ci0 + ci)*HWSZ;
        float r[9];
        #pragma unroll
        for (int dy = 0; dy < 3; dy++) {
            int yy = h + dy - 1;
            bool yok = ((unsigned)yy < HH);
            #pragma unroll
            for (int dx = 0; dx < 3; dx++) {
                int xx = x + dx - 1;
                r[dy*3+dx] = (yok && (unsigned)xx < WW) ? __ldg(ip + yy*WW + xx) : 0.f;
            }
        }
        const float4* wq = (const float4*)(g_maskwt + (size_t)(ci0+ci)*12);
        float4 wa  = __ldg(wq);
        float4 wb4 = __ldg(wq+1);
        float4 wc  = __ldg(wq+2);
        acc += r[0]*wa.x + r[1]*wa.y + r[2]*wa.z
             + r[3]*wa.w + r[4]*wb4.x + r[5]*wb4.y
             + r[6]*wb4.z + r[7]*wb4.w + r[8]*wc.x;
    }
    g_maskp[(size_t)(ch*BN + b)*HWSZ + hw] = acc;
}

__global__ __launch_bounds__(256) void maskconv_reduce(
    const float* __restrict__ bias, float* __restrict__ out)
{
    int i = blockIdx.x*256 + threadIdx.x;
    if (i >= BN*HWSZ) return;
    float v = bias[0];
    #pragma unroll
    for (int ch = 0; ch < 4; ch++)
        v += g_maskp[(size_t)ch*BN*HWSZ + i];
    out[i] = v;
}

// ---------------- launch ----------------
extern "C" void kernel_launch(void* const* d_in, const int* in_sizes, int n_in,
                              void* d_out, int out_size)
{
    const float* x       = (const float*)d_in[0];
    const float* y       = (const float*)d_in[1];
    const float* conv_w  = (const float*)d_in[2];
    const float* conv_b  = (const float*)d_in[3];
    const float* off_w   = (const float*)d_in[4];
    const float* off_b   = (const float*)d_in[5];
    const float* dcn_w   = (const float*)d_in[6];
    const float* dcn_b   = (const float*)d_in[7];
    const float* conv2_w = (const float*)d_in[8];
    const float* conv2_b = (const float*)d_in[9];
    const float* bn_g    = (const float*)d_in[10];
    const float* bn_b    = (const float*)d_in[11];
    const float* mask_w  = (const float*)d_in[12];
    const float* mask_b  = (const float*)d_in[13];
    float* out = (float*)d_out;

    float *p_h1, *p_h2, *p_h3, *p_col, *p_samp;
    uint8_t *p_w1g, *p_w2g, *p_wdg;
    cudaGetSymbolAddress((void**)&p_h1,  g_h1);
    cudaGetSymbolAddress((void**)&p_h2,  g_h2);
    cudaGetSymbolAddress((void**)&p_h3,  g_h3);
    cudaGetSymbolAddress((void**)&p_col, g_col);
    cudaGetSymbolAddress((void**)&p_samp, g_samp);
    cudaGetSymbolAddress((void**)&p_w1g, g_w1g);
    cudaGetSymbolAddress((void**)&p_w2g, g_w2g);
    cudaGetSymbolAddress((void**)&p_wdg, g_wdg);

    // weight prep
    prep_wgemm<<<(128*2304 + 255)/256, 256>>>(conv_w,  p_w1g, 256, 0);
    prep_wgemm<<<(128*1152 + 255)/256, 256>>>(conv2_w, p_w2g, 128, 0);
    prep_wgemm<<<(128*1152 + 255)/256, 256>>>(dcn_w,   p_wdg, 128, 1);
    prep_offw<<<(CC*18 + 255)/256, 256>>>(off_w);
    prep_maskw<<<1, 256>>>(mask_w);

    // conv1: im2col(concat(x,y)) + GEMM (K=2304 -> 72 stages)
    im2col<<<dim3(2304, BN), 256>>>(x, y, p_col, 256);
    gemm_mma<<<dim3(49, BN), 256>>>(p_col, p_w1g, conv_b, p_h1, 72);

    // offset conv 128 -> 18
    offconv_part<<<dim3(14, BN, 4), dim3(56, 4)>>>();
    offconv_reduce<<<(BN*18*HWSZ + 255)/256, 256>>>(off_b);

    // deformable sampling + dcn GEMM (K=1152 -> 36 stages)
    sample_k<<<dim3(HH, BN, 9), 64>>>();
    gemm_mma<<<dim3(49, BN), 256>>>(p_samp, p_wdg, dcn_b, p_h2, 36);

    // conv2: im2col(h2) + GEMM (K=1152)
    im2col<<<dim3(1152, BN), 256>>>(p_h2, p_h2, p_col, 128);
    gemm_mma<<<dim3(49, BN), 256>>>(p_col, p_w2g, conv2_b, p_h3, 36);

    // batch norm + GELU -> d_out
    bnstats<<<CC, 256>>>();
    bngelu<<<(BN*CC*HWSZ + 255)/256, 256>>>(bn_g, bn_b, out);

    // mask conv -> d_out tail
    maskconv_part<<<dim3(14, BN, 4), dim3(56, 4)>>>(out);
    maskconv_reduce<<<(BN*HWSZ + 255)/256, 256>>>(mask_b, out + (size_t)BN*CC*HWSZ);

    (void)in_sizes; (void)n_in; (void)out_size;
}

// round 6
// speedup vs baseline: 3.9016x; 1.4918x over previous
#include <cuda_runtime.h>
#include <cuda_bf16.h>
#include <math.h>
#include <stdint.h>

#define BN 8
#define CC 128
#define HH 56
#define WW 56
#define HWSZ (HH*WW)

// ---------------- scratch ----------------
__device__ __align__(16) float g_h1[BN*CC*HWSZ];
__device__ __align__(16) float g_off[BN*18*HWSZ];
__device__ __align__(16) float g_offp[4*BN*18*HWSZ];
__device__ __align__(16) float g_h2[BN*CC*HWSZ];
__device__ __align__(16) float g_h3[BN*CC*HWSZ];
__device__ __align__(16) float g_maskp[4*BN*HWSZ];
__device__ float g_mean[CC];
__device__ float g_rstd[CC];
__device__ __align__(16) uint8_t g_w1g[144*8192];
__device__ __align__(16) uint8_t g_w2g[72*8192];
__device__ __align__(16) uint8_t g_wdg[72*8192];
__device__ __align__(16) float g_offwt[CC*18*12];
__device__ __align__(16) float g_maskwt[CC*12];

__device__ __forceinline__ uint32_t smem_u32(const void* p) {
    uint32_t a;
    asm("{ .reg .u64 t; cvta.to.shared.u64 t, %1; cvt.u32.u64 %0, t; }" : "=r"(a) : "l"(p));
    return a;
}
__device__ __forceinline__ uint16_t bf16_bits(float x) {
    __nv_bfloat16 h = __float2bfloat16(x);
    uint16_t u; *(__nv_bfloat16*)&u = h; return u;
}
__device__ __forceinline__ float bf16_val(uint16_t u) {
    __nv_bfloat16 h; *(uint16_t*)&h = u; return __bfloat162float(h);
}

// ---------------- fused GEMM ----------------
// MODE 0: conv over concat(srcA,srcB)  (CIN=256)
// MODE 1: conv over srcA               (CIN=128)
// MODE 2: dcn - bilinear gather from g_h1 via g_off (CIN=128)
template<int CIN, int MODE>
__global__ __launch_bounds__(256) void gemm_fused(
    const float* __restrict__ srcA, const float* __restrict__ srcB,
    const uint8_t* __restrict__ Ag,
    const float* __restrict__ bias, float* __restrict__ out)
{
    constexpr int NST = CIN * 9 / 32;
    __shared__ uint16_t sB[2][2][32][72];     // [buf][term][k][px]
    const int tid = threadIdx.x, lid = tid & 31, wid = tid >> 5;
    const int warpM = wid & 3, warpN = wid >> 2;
    const int b = blockIdx.y;
    const int px0 = blockIdx.x * 64;

    // staging mapping: px fixed per thread
    const int spx = tid & 63;
    const int rbase = (tid >> 6) * 8;
    const int shw = px0 + spx;
    const int sy = shw / WW, sx = shw - sy * WW;

    float c[2][4][4];
    #pragma unroll
    for (int mt = 0; mt < 2; mt++)
        #pragma unroll
        for (int nt = 0; nt < 4; nt++)
            #pragma unroll
            for (int r = 0; r < 4; r++) c[mt][nt][r] = 0.f;

    const int lmtx = lid >> 3, lrow = lid & 7;
    const int lk = ((lmtx & 1) << 3) + lrow;
    const int ln = warpN * 32 + ((lmtx >> 1) << 3);

    // ---- staging load (registers) ----
    float v[8];
    auto stage_load = [&](int s) {
        if (MODE <= 1) {
            constexpr int PER = CIN / 32;
            int tap = s / PER, ci0 = (s % PER) * 32;
            int dy = tap / 3 - 1, dx = tap % 3 - 1;
            int yy = sy + dy, xx = sx + dx;
            bool ok = ((unsigned)yy < HH) && ((unsigned)xx < WW);
            int off = yy * WW + xx;
            #pragma unroll
            for (int i = 0; i < 8; i++) {
                int ci = ci0 + rbase + i;
                const float* src;
                if (MODE == 0)
                    src = (ci < 128) ? srcA + (size_t)(b*128+ci)*HWSZ
                                     : srcB + (size_t)(b*128+ci-128)*HWSZ;
                else
                    src = srcA + (size_t)(b*128+ci)*HWSZ;
                v[i] = ok ? __ldg(src + off) : 0.f;
            }
        } else {
            int k = s >> 2, c0 = (s & 3) * 32;
            float oy = __ldg(g_off + (size_t)(b*18 + 2*k    )*HWSZ + shw);
            float ox = __ldg(g_off + (size_t)(b*18 + 2*k + 1)*HWSZ + shw);
            float py  = (float)(sy + k/3 - 1) + oy;
            float pxf = (float)(sx + k%3 - 1) + ox;
            float y0f = floorf(py), x0f = floorf(pxf);
            float wy1 = py - y0f, wy0 = 1.f - wy1;
            float wx1 = pxf - x0f, wx0 = 1.f - wx1;
            int y0 = (int)y0f, x0i = (int)x0f;
            int idx[4]; float wv[4];
            int ys[4] = {y0, y0, y0+1, y0+1};
            int xs[4] = {x0i, x0i+1, x0i, x0i+1};
            float ws[4] = {wy0*wx0, wy0*wx1, wy1*wx0, wy1*wx1};
            #pragma unroll
            for (int t = 0; t < 4; t++) {
                bool va = (ys[t] >= 0) && (ys[t] <= HH-1) && (xs[t] >= 0) && (xs[t] <= WW-1);
                int iy = min(max(ys[t], 0), HH-1);
                int ix = min(max(xs[t], 0), WW-1);
                idx[t] = iy*WW + ix;
                wv[t]  = va ? ws[t] : 0.f;
            }
            #pragma unroll
            for (int i = 0; i < 8; i++) {
                const float* xp = g_h1 + (size_t)(b*128 + c0 + rbase + i)*HWSZ;
                v[i] = wv[0]*__ldg(xp+idx[0]) + wv[1]*__ldg(xp+idx[1])
                     + wv[2]*__ldg(xp+idx[2]) + wv[3]*__ldg(xp+idx[3]);
            }
        }
    };

    stage_load(0);

    for (int stage = 0; stage < NST; stage++) {
        const int buf = stage & 1;
        // store regs -> smem (bf16 hi/lo)
        #pragma unroll
        for (int i = 0; i < 8; i++) {
            uint16_t hb = bf16_bits(v[i]);
            uint16_t lb = bf16_bits(v[i] - bf16_val(hb));
            sB[buf][0][rbase + i][spx] = hb;
            sB[buf][1][rbase + i][spx] = lb;
        }
        __syncthreads();
        if (stage + 1 < NST) stage_load(stage + 1);

        const uint32_t sbh = smem_u32(&sB[buf][0][0][0]);
        const uint32_t sbl = smem_u32(&sB[buf][1][0][0]);
        #pragma unroll
        for (int s = 0; s < 2; s++) {
            const int kk = stage * 2 + s;
            uint4 ah[2], al[2];
            #pragma unroll
            for (int mt = 0; mt < 2; mt++) {
                const uint4* ap = (const uint4*)Ag + (size_t)((kk * 8 + warpM * 2 + mt) * 2) * 32 + lid;
                ah[mt] = __ldg(ap);
                al[mt] = __ldg(ap + 32);
            }
            uint32_t bh[2][4], bl[2][4];
            #pragma unroll
            for (int q = 0; q < 2; q++) {
                uint32_t off = (uint32_t)((s * 16 + lk) * 72 + ln + q * 16) * 2;
                asm volatile("ldmatrix.sync.aligned.m8n8.x4.trans.shared.b16 {%0,%1,%2,%3}, [%4];"
                    : "=r"(bh[q][0]), "=r"(bh[q][1]), "=r"(bh[q][2]), "=r"(bh[q][3]) : "r"(sbh + off));
                asm volatile("ldmatrix.sync.aligned.m8n8.x4.trans.shared.b16 {%0,%1,%2,%3}, [%4];"
                    : "=r"(bl[q][0]), "=r"(bl[q][1]), "=r"(bl[q][2]), "=r"(bl[q][3]) : "r"(sbl + off));
            }
            #pragma unroll
            for (int mt = 0; mt < 2; mt++) {
                #pragma unroll
                for (int q = 0; q < 2; q++) {
                    #pragma unroll
                    for (int h = 0; h < 2; h++) {
                        float* cc = c[mt][q * 2 + h];
                        #define MMA(AF, B0, B1) \
                            asm volatile("mma.sync.aligned.m16n8k16.row.col.f32.bf16.bf16.f32 " \
                                "{%0,%1,%2,%3}, {%4,%5,%6,%7}, {%8,%9}, {%0,%1,%2,%3};" \
                                : "+f"(cc[0]), "+f"(cc[1]), "+f"(cc[2]), "+f"(cc[3]) \
                                : "r"(AF.x), "r"(AF.y), "r"(AF.z), "r"(AF.w), "r"(B0), "r"(B1))
                        MMA(ah[mt], bh[q][h * 2], bh[q][h * 2 + 1]);
                        MMA(ah[mt], bl[q][h * 2], bl[q][h * 2 + 1]);
                        MMA(al[mt], bh[q][h * 2], bh[q][h * 2 + 1]);
                        #undef MMA
                    }
                }
            }
        }
    }

    #pragma unroll
    for (int mt = 0; mt < 2; mt++) {
        int row = warpM * 32 + mt * 16 + (lid >> 2);
        float bi0 = bias[row], bi8 = bias[row + 8];
        #pragma unroll
        for (int nt = 0; nt < 4; nt++) {
            int col = warpN * 32 + nt * 8 + (lid & 3) * 2;
            float* o0 = out + (size_t)(b * 128 + row) * HWSZ + px0 + col;
            *(float2*)o0 = make_float2(c[mt][nt][0] + bi0, c[mt][nt][1] + bi0);
            *(float2*)(o0 + 8 * HWSZ) = make_float2(c[mt][nt][2] + bi8, c[mt][nt][3] + bi8);
        }
    }
}

// ---------------- weight prep (fragment order, hi/lo) ----------------
__global__ void prep_wgemm(const float* __restrict__ w, uint8_t* __restrict__ dst, int CIN, int mode) {
    int K = CIN * 9;
    int i = blockIdx.x * 256 + threadIdx.x;
    if (i >= 128 * K) return;
    int co = i / K, kg = i % K;
    float v;
    if (mode == 0) { int tap = kg / CIN, ci = kg % CIN; v = w[((size_t)co * CIN + ci) * 9 + tap]; }
    else           { int k = kg >> 7,   c  = kg & 127;  v = w[((size_t)co * 128 + c) * 9 + k]; }
    uint16_t hb = bf16_bits(v);
    uint16_t lb = bf16_bits(v - bf16_val(hb));
    int kk = kg >> 4, kin = kg & 15;
    int mt = co >> 4, row = co & 15;
    int lane = (row & 7) * 4 + ((kin & 7) >> 1);
    int reg = (row >> 3) + ((kin >> 3) << 1);
    int half = kin & 1;
    uint16_t* d16 = (uint16_t*)dst;
    size_t base = ((size_t)(kk * 8 + mt) * 2) * 128 + lane * 4 + reg;
    d16[base * 2 + half] = hb;
    d16[(base + 128) * 2 + half] = lb;
}

__global__ void prep_offw(const float* __restrict__ w) {
    int i = blockIdx.x*256 + threadIdx.x;
    if (i < CC*18) {
        int ci = i / 18, co = i % 18;
        #pragma unroll
        for (int k = 0; k < 9; k++) g_offwt[i*12+k] = w[(co*CC+ci)*9+k];
        g_offwt[i*12+9]=0.f; g_offwt[i*12+10]=0.f; g_offwt[i*12+11]=0.f;
    }
}
__global__ void prep_maskw(const float* __restrict__ w) {
    int i = blockIdx.x*256 + threadIdx.x;
    if (i < CC) {
        #pragma unroll
        for (int k = 0; k < 9; k++) g_maskwt[i*12+k] = w[i*9+k];
        g_maskwt[i*12+9]=0.f; g_maskwt[i*12+10]=0.f; g_maskwt[i*12+11]=0.f;
    }
}

// ---------------- offset conv (split-ci) ----------------
__global__ __launch_bounds__(224) void offconv_part()
{
    int x  = threadIdx.x;
    int h  = blockIdx.x*4 + threadIdx.y;
    int b  = blockIdx.y;
    int ch = blockIdx.z;
    int ci0 = ch*32;
    int hw = h*WW + x;

    float acc[18];
    #pragma unroll
    for (int co = 0; co < 18; co++) acc[co] = 0.f;

    for (int ci = 0; ci < 32; ci++) {
        const float* ip = g_h1 + (size_t)(b*128 + ci0 + ci)*HWSZ;
        float r[9];
        #pragma unroll
        for (int dy = 0; dy < 3; dy++) {
            int yy = h + dy - 1;
            bool yok = ((unsigned)yy < HH);
            #pragma unroll
            for (int dx = 0; dx < 3; dx++) {
                int xx = x + dx - 1;
                r[dy*3+dx] = (yok && (unsigned)xx < WW) ? __ldg(ip + yy*WW + xx) : 0.f;
            }
        }
        const float4* wbase = (const float4*)(g_offwt + (size_t)(ci0+ci)*18*12);
        #pragma unroll
        for (int co = 0; co < 18; co++) {
            float4 wa  = __ldg(wbase + co*3);
            float4 wb4 = __ldg(wbase + co*3 + 1);
            float4 wc  = __ldg(wbase + co*3 + 2);
            acc[co] += r[0]*wa.x + r[1]*wa.y + r[2]*wa.z
                     + r[3]*wa.w + r[4]*wb4.x + r[5]*wb4.y
                     + r[6]*wb4.z + r[7]*wb4.w + r[8]*wc.x;
        }
    }
    #pragma unroll
    for (int co = 0; co < 18; co++)
        g_offp[(size_t)((ch*BN + b)*18 + co)*HWSZ + hw] = acc[co];
}

__global__ __launch_bounds__(256) void offconv_reduce(const float* __restrict__ bias)
{
    int i = blockIdx.x*256 + threadIdx.x;
    if (i >= BN*18*HWSZ) return;
    int co = (i / HWSZ) % 18;
    float v = bias[co];
    #pragma unroll
    for (int ch = 0; ch < 4; ch++)
        v += g_offp[(size_t)ch*BN*18*HWSZ + i];
    g_off[i] = v;
}

// ---------------- BN stats ----------------
__global__ __launch_bounds__(256) void bnstats()
{
    int c = blockIdx.x;
    int tid = threadIdx.x;
    float s = 0.f, s2 = 0.f;
    for (int i = tid; i < BN*HWSZ; i += 256) {
        int b = i / HWSZ, hw = i % HWSZ;
        float v = g_h3[(size_t)(b*128 + c)*HWSZ + hw];
        s += v; s2 += v*v;
    }
    __shared__ float sh[256], sh2[256];
    sh[tid] = s; sh2[tid] = s2;
    __syncthreads();
    for (int o = 128; o > 0; o >>= 1) {
        if (tid < o) { sh[tid] += sh[tid+o]; sh2[tid] += sh2[tid+o]; }
        __syncthreads();
    }
    if (tid == 0) {
        float n = (float)(BN*HWSZ);
        float mean = sh[0]/n;
        float var  = sh2[0]/n - mean*mean;
        g_mean[c] = mean;
        g_rstd[c] = rsqrtf(var + 1e-5f);
    }
}

__global__ __launch_bounds__(256) void bngelu(
    const float* __restrict__ gamma, const float* __restrict__ beta,
    float* __restrict__ out)
{
    int i = blockIdx.x*256 + threadIdx.x;
    if (i >= BN*CC*HWSZ) return;
    int c = (i / HWSZ) & 127;
    float v = g_h3[i];
    v = (v - g_mean[c]) * g_rstd[c] * gamma[c] + beta[c];
    out[i] = 0.5f * v * (1.f + erff(v * 0.70710678118654752440f));
}

// ---------------- mask conv (split-ci) ----------------
__global__ __launch_bounds__(224) void maskconv_part(const float* __restrict__ hsrc)
{
    int x  = threadIdx.x;
    int h  = blockIdx.x*4 + threadIdx.y;
    int b  = blockIdx.y;
    int ch = blockIdx.z;
    int ci0 = ch*32;
    int hw = h*WW + x;

    float acc = 0.f;
    for (int ci = 0; ci < 32; ci++) {
        const float* ip = hsrc + (size_t)(b*128 + ci0 + ci)*HWSZ;
        float r[9];
        #pragma unroll
        for (int dy = 0; dy < 3; dy++) {
            int yy = h + dy - 1;
            bool yok = ((unsigned)yy < HH);
            #pragma unroll
            for (int dx = 0; dx < 3; dx++) {
                int xx = x + dx - 1;
                r[dy*3+dx] = (yok && (unsigned)xx < WW) ? __ldg(ip + yy*WW + xx) : 0.f;
            }
        }
        const float4* wq = (const float4*)(g_maskwt + (size_t)(ci0+ci)*12);
        float4 wa  = __ldg(wq);
        float4 wb4 = __ldg(wq+1);
        float4 wc  = __ldg(wq+2);
        acc += r[0]*wa.x + r[1]*wa.y + r[2]*wa.z
             + r[3]*wa.w + r[4]*wb4.x + r[5]*wb4.y
             + r[6]*wb4.z + r[7]*wb4.w + r[8]*wc.x;
    }
    g_maskp[(size_t)(ch*BN + b)*HWSZ + hw] = acc;
}

__global__ __launch_bounds__(256) void maskconv_reduce(
    const float* __restrict__ bias, float* __restrict__ out)
{
    int i = blockIdx.x*256 + threadIdx.x;
    if (i >= BN*HWSZ) return;
    float v = bias[0];
    #pragma unroll
    for (int ch = 0; ch < 4; ch++)
        v += g_maskp[(size_t)ch*BN*HWSZ + i];
    out[i] = v;
}

// ---------------- launch ----------------
extern "C" void kernel_launch(void* const* d_in, const int* in_sizes, int n_in,
                              void* d_out, int out_size)
{
    const float* x       = (const float*)d_in[0];
    const float* y       = (const float*)d_in[1];
    const float* conv_w  = (const float*)d_in[2];
    const float* conv_b  = (const float*)d_in[3];
    const float* off_w   = (const float*)d_in[4];
    const float* off_b   = (const float*)d_in[5];
    const float* dcn_w   = (const float*)d_in[6];
    const float* dcn_b   = (const float*)d_in[7];
    const float* conv2_w = (const float*)d_in[8];
    const float* conv2_b = (const float*)d_in[9];
    const float* bn_g    = (const float*)d_in[10];
    const float* bn_b    = (const float*)d_in[11];
    const float* mask_w  = (const float*)d_in[12];
    const float* mask_b  = (const float*)d_in[13];
    float* out = (float*)d_out;

    float *p_h1, *p_h2, *p_h3;
    uint8_t *p_w1g, *p_w2g, *p_wdg;
    cudaGetSymbolAddress((void**)&p_h1,  g_h1);
    cudaGetSymbolAddress((void**)&p_h2,  g_h2);
    cudaGetSymbolAddress((void**)&p_h3,  g_h3);
    cudaGetSymbolAddress((void**)&p_w1g, g_w1g);
    cudaGetSymbolAddress((void**)&p_w2g, g_w2g);
    cudaGetSymbolAddress((void**)&p_wdg, g_wdg);

    // weight prep
    prep_wgemm<<<(128*2304 + 255)/256, 256>>>(conv_w,  p_w1g, 256, 0);
    prep_wgemm<<<(128*1152 + 255)/256, 256>>>(conv2_w, p_w2g, 128, 0);
    prep_wgemm<<<(128*1152 + 255)/256, 256>>>(dcn_w,   p_wdg, 128, 1);
    prep_offw<<<(CC*18 + 255)/256, 256>>>(off_w);
    prep_maskw<<<1, 256>>>(mask_w);

    // conv1: fused im2col GEMM over concat(x,y)
    gemm_fused<256, 0><<<dim3(49, BN), 256>>>(x, y, p_w1g, conv_b, p_h1);

    // offset conv 128 -> 18
    offconv_part<<<dim3(14, BN, 4), dim3(56, 4)>>>();
    offconv_reduce<<<(BN*18*HWSZ + 255)/256, 256>>>(off_b);

    // dcn: fused bilinear-gather GEMM
    gemm_fused<128, 2><<<dim3(49, BN), 256>>>(nullptr, nullptr, p_wdg, dcn_b, p_h2);

    // conv2: fused im2col GEMM
    gemm_fused<128, 1><<<dim3(49, BN), 256>>>(p_h2, nullptr, p_w2g, conv2_b, p_h3);

    // batch norm + GELU -> d_out
    bnstats<<<CC, 256>>>();
    bngelu<<<(BN*CC*HWSZ + 255)/256, 256>>>(bn_g, bn_b, out);

    // mask conv -> d_out tail
    maskconv_part<<<dim3(14, BN, 4), dim3(56, 4)>>>(out);
    maskconv_reduce<<<(BN*HWSZ + 255)/256, 256>>>(mask_b, out + (size_t)BN*CC*HWSZ);

    (void)in_sizes; (void)n_in; (void)out_size;
}

// round 7
// speedup vs baseline: 4.6647x; 1.1956x over previous
#include <cuda_runtime.h>
#include <cuda_fp16.h>
#include <math.h>
#include <stdint.h>

#define BN 8
#define CC 128
#define HH 56
#define WW 56
#define HWSZ (HH*WW)

// ---------------- scratch ----------------
__device__ __align__(16) float g_h1[BN*CC*HWSZ];
__device__ __align__(16) float g_off[BN*18*HWSZ];
__device__ __align__(16) float g_offp[4*BN*18*HWSZ];
__device__ __align__(16) float g_h2[BN*CC*HWSZ];
__device__ __align__(16) float g_h3[BN*CC*HWSZ];
__device__ __align__(16) float g_maskp[4*BN*HWSZ];
__device__ float g_mean[CC];
__device__ float g_rstd[CC];
__device__ __align__(16) uint8_t g_w1g[144*8192];
__device__ __align__(16) uint8_t g_w2g[72*8192];
__device__ __align__(16) uint8_t g_wdg[72*8192];
__device__ __align__(16) float g_offwt[CC*18*12];
__device__ __align__(16) float g_maskwt[CC*12];

__device__ __forceinline__ uint32_t smem_u32(const void* p) {
    uint32_t a;
    asm("{ .reg .u64 t; cvta.to.shared.u64 t, %1; cvt.u32.u64 %0, t; }" : "=r"(a) : "l"(p));
    return a;
}
__device__ __forceinline__ uint16_t f16_bits(float x) {
    return __half_as_ushort(__float2half_rn(x));
}
__device__ __forceinline__ float f16_val(uint16_t u) {
    return __half2float(__ushort_as_half(u));
}

// ---------------- fused GEMM (fp16: A hi/lo pre-split, B single) ----------------
// MODE 0: conv over concat(srcA,srcB)  (CIN=256)
// MODE 1: conv over srcA               (CIN=128)
// MODE 2: dcn - bilinear gather from g_h1 via g_off (CIN=128)
template<int CIN, int MODE>
__global__ __launch_bounds__(256) void gemm_fused(
    const float* __restrict__ srcA, const float* __restrict__ srcB,
    const uint8_t* __restrict__ Ag,
    const float* __restrict__ bias, float* __restrict__ out)
{
    constexpr int NST = CIN * 9 / 32;
    __shared__ uint16_t sB[2][32][72];       // [buf][k][px], single fp16 plane
    const int tid = threadIdx.x, lid = tid & 31, wid = tid >> 5;
    const int warpM = wid & 3, warpN = wid >> 2;
    const int b = blockIdx.y;
    const int px0 = blockIdx.x * 64;

    const int spx = tid & 63;
    const int rbase = (tid >> 6) * 8;
    const int shw = px0 + spx;
    const int sy = shw / WW, sx = shw - sy * WW;

    float c[2][4][4];
    #pragma unroll
    for (int mt = 0; mt < 2; mt++)
        #pragma unroll
        for (int nt = 0; nt < 4; nt++)
            #pragma unroll
            for (int r = 0; r < 4; r++) c[mt][nt][r] = 0.f;

    const int lmtx = lid >> 3, lrow = lid & 7;
    const int lk = ((lmtx & 1) << 3) + lrow;
    const int ln = warpN * 32 + ((lmtx >> 1) << 3);

    float v[8];
    auto stage_load = [&](int s) {
        if (MODE <= 1) {
            constexpr int PER = CIN / 32;
            int tap = s / PER, ci0 = (s % PER) * 32;
            int dy = tap / 3 - 1, dx = tap % 3 - 1;
            int yy = sy + dy, xx = sx + dx;
            bool ok = ((unsigned)yy < HH) && ((unsigned)xx < WW);
            int off = yy * WW + xx;
            #pragma unroll
            for (int i = 0; i < 8; i++) {
                int ci = ci0 + rbase + i;
                const float* src;
                if (MODE == 0)
                    src = (ci < 128) ? srcA + (size_t)(b*128+ci)*HWSZ
                                     : srcB + (size_t)(b*128+ci-128)*HWSZ;
                else
                    src = srcA + (size_t)(b*128+ci)*HWSZ;
                v[i] = ok ? __ldg(src + off) : 0.f;
            }
        } else {
            int k = s >> 2, c0 = (s & 3) * 32;
            float oy = __ldg(g_off + (size_t)(b*18 + 2*k    )*HWSZ + shw);
            float ox = __ldg(g_off + (size_t)(b*18 + 2*k + 1)*HWSZ + shw);
            float py  = (float)(sy + k/3 - 1) + oy;
            float pxf = (float)(sx + k%3 - 1) + ox;
            float y0f = floorf(py), x0f = floorf(pxf);
            float wy1 = py - y0f, wy0 = 1.f - wy1;
            float wx1 = pxf - x0f, wx0 = 1.f - wx1;
            int y0 = (int)y0f, x0i = (int)x0f;
            int idx[4]; float wv[4];
            int ys[4] = {y0, y0, y0+1, y0+1};
            int xs[4] = {x0i, x0i+1, x0i, x0i+1};
            float ws[4] = {wy0*wx0, wy0*wx1, wy1*wx0, wy1*wx1};
            #pragma unroll
            for (int t = 0; t < 4; t++) {
                bool va = (ys[t] >= 0) && (ys[t] <= HH-1) && (xs[t] >= 0) && (xs[t] <= WW-1);
                int iy = min(max(ys[t], 0), HH-1);
                int ix = min(max(xs[t], 0), WW-1);
                idx[t] = iy*WW + ix;
                wv[t]  = va ? ws[t] : 0.f;
            }
            #pragma unroll
            for (int i = 0; i < 8; i++) {
                const float* xp = g_h1 + (size_t)(b*128 + c0 + rbase + i)*HWSZ;
                v[i] = wv[0]*__ldg(xp+idx[0]) + wv[1]*__ldg(xp+idx[1])
                     + wv[2]*__ldg(xp+idx[2]) + wv[3]*__ldg(xp+idx[3]);
            }
        }
    };

    stage_load(0);

    for (int stage = 0; stage < NST; stage++) {
        const int buf = stage & 1;
        #pragma unroll
        for (int i = 0; i < 8; i++)
            sB[buf][rbase + i][spx] = f16_bits(v[i]);
        __syncthreads();
        if (stage + 1 < NST) stage_load(stage + 1);

        const uint32_t sbh = smem_u32(&sB[buf][0][0]);
        #pragma unroll
        for (int s = 0; s < 2; s++) {
            const int kk = stage * 2 + s;
            uint4 ah[2], al[2];
            #pragma unroll
            for (int mt = 0; mt < 2; mt++) {
                const uint4* ap = (const uint4*)Ag + (size_t)((kk * 8 + warpM * 2 + mt) * 2) * 32 + lid;
                ah[mt] = __ldg(ap);
                al[mt] = __ldg(ap + 32);
            }
            uint32_t bh[2][4];
            #pragma unroll
            for (int q = 0; q < 2; q++) {
                uint32_t off = (uint32_t)((s * 16 + lk) * 72 + ln + q * 16) * 2;
                asm volatile("ldmatrix.sync.aligned.m8n8.x4.trans.shared.b16 {%0,%1,%2,%3}, [%4];"
                    : "=r"(bh[q][0]), "=r"(bh[q][1]), "=r"(bh[q][2]), "=r"(bh[q][3]) : "r"(sbh + off));
            }
            #pragma unroll
            for (int mt = 0; mt < 2; mt++) {
                #pragma unroll
                for (int q = 0; q < 2; q++) {
                    #pragma unroll
                    for (int h = 0; h < 2; h++) {
                        float* cc = c[mt][q * 2 + h];
                        #define MMA(AF, B0, B1) \
                            asm volatile("mma.sync.aligned.m16n8k16.row.col.f32.f16.f16.f32 " \
                                "{%0,%1,%2,%3}, {%4,%5,%6,%7}, {%8,%9}, {%0,%1,%2,%3};" \
                                : "+f"(cc[0]), "+f"(cc[1]), "+f"(cc[2]), "+f"(cc[3]) \
                                : "r"(AF.x), "r"(AF.y), "r"(AF.z), "r"(AF.w), "r"(B0), "r"(B1))
                        MMA(ah[mt], bh[q][h * 2], bh[q][h * 2 + 1]);
                        MMA(al[mt], bh[q][h * 2], bh[q][h * 2 + 1]);
                        #undef MMA
                    }
                }
            }
        }
    }

    #pragma unroll
    for (int mt = 0; mt < 2; mt++) {
        int row = warpM * 32 + mt * 16 + (lid >> 2);
        float bi0 = bias[row], bi8 = bias[row + 8];
        #pragma unroll
        for (int nt = 0; nt < 4; nt++) {
            int col = warpN * 32 + nt * 8 + (lid & 3) * 2;
            float* o0 = out + (size_t)(b * 128 + row) * HWSZ + px0 + col;
            *(float2*)o0 = make_float2(c[mt][nt][0] + bi0, c[mt][nt][1] + bi0);
            *(float2*)(o0 + 8 * HWSZ) = make_float2(c[mt][nt][2] + bi8, c[mt][nt][3] + bi8);
        }
    }
}

// ---------------- weight prep (fragment order, fp16 hi/lo) ----------------
__global__ void prep_wgemm(const float* __restrict__ w, uint8_t* __restrict__ dst, int CIN, int mode) {
    int K = CIN * 9;
    int i = blockIdx.x * 256 + threadIdx.x;
    if (i >= 128 * K) return;
    int co = i / K, kg = i % K;
    float v;
    if (mode == 0) { int tap = kg / CIN, ci = kg % CIN; v = w[((size_t)co * CIN + ci) * 9 + tap]; }
    else           { int k = kg >> 7,   c  = kg & 127;  v = w[((size_t)co * 128 + c) * 9 + k]; }
    uint16_t hb = f16_bits(v);
    uint16_t lb = f16_bits(v - f16_val(hb));
    int kk = kg >> 4, kin = kg & 15;
    int mt = co >> 4, row = co & 15;
    int lane = (row & 7) * 4 + ((kin & 7) >> 1);
    int reg = (row >> 3) + ((kin >> 3) << 1);
    int half = kin & 1;
    uint16_t* d16 = (uint16_t*)dst;
    size_t base = ((size_t)(kk * 8 + mt) * 2) * 128 + lane * 4 + reg;
    d16[base * 2 + half] = hb;
    d16[(base + 128) * 2 + half] = lb;
}

__global__ void prep_offw(const float* __restrict__ w) {
    int i = blockIdx.x*256 + threadIdx.x;
    if (i < CC*18) {
        int ci = i / 18, co = i % 18;
        #pragma unroll
        for (int k = 0; k < 9; k++) g_offwt[i*12+k] = w[(co*CC+ci)*9+k];
        g_offwt[i*12+9]=0.f; g_offwt[i*12+10]=0.f; g_offwt[i*12+11]=0.f;
    }
}
__global__ void prep_maskw(const float* __restrict__ w) {
    int i = blockIdx.x*256 + threadIdx.x;
    if (i < CC) {
        #pragma unroll
        for (int k = 0; k < 9; k++) g_maskwt[i*12+k] = w[i*9+k];
        g_maskwt[i*12+9]=0.f; g_maskwt[i*12+10]=0.f; g_maskwt[i*12+11]=0.f;
    }
}

// ---------------- offset conv (split-ci) ----------------
__global__ __launch_bounds__(224) void offconv_part()
{
    int x  = threadIdx.x;
    int h  = blockIdx.x*4 + threadIdx.y;
    int b  = blockIdx.y;
    int ch = blockIdx.z;
    int ci0 = ch*32;
    int hw = h*WW + x;

    float acc[18];
    #pragma unroll
    for (int co = 0; co < 18; co++) acc[co] = 0.f;

    for (int ci = 0; ci < 32; ci++) {
        const float* ip = g_h1 + (size_t)(b*128 + ci0 + ci)*HWSZ;
        float r[9];
        #pragma unroll
        for (int dy = 0; dy < 3; dy++) {
            int yy = h + dy - 1;
            bool yok = ((unsigned)yy < HH);
            #pragma unroll
            for (int dx = 0; dx < 3; dx++) {
                int xx = x + dx - 1;
                r[dy*3+dx] = (yok && (unsigned)xx < WW) ? __ldg(ip + yy*WW + xx) : 0.f;
            }
        }
        const float4* wbase = (const float4*)(g_offwt + (size_t)(ci0+ci)*18*12);
        #pragma unroll
        for (int co = 0; co < 18; co++) {
            float4 wa  = __ldg(wbase + co*3);
            float4 wb4 = __ldg(wbase + co*3 + 1);
            float4 wc  = __ldg(wbase + co*3 + 2);
            acc[co] += r[0]*wa.x + r[1]*wa.y + r[2]*wa.z
                     + r[3]*wa.w + r[4]*wb4.x + r[5]*wb4.y
                     + r[6]*wb4.z + r[7]*wb4.w + r[8]*wc.x;
        }
    }
    #pragma unroll
    for (int co = 0; co < 18; co++)
        g_offp[(size_t)((ch*BN + b)*18 + co)*HWSZ + hw] = acc[co];
}

__global__ __launch_bounds__(256) void offconv_reduce(const float* __restrict__ bias)
{
    int i = blockIdx.x*256 + threadIdx.x;
    if (i >= BN*18*HWSZ) return;
    int co = (i / HWSZ) % 18;
    float v = bias[co];
    #pragma unroll
    for (int ch = 0; ch < 4; ch++)
        v += g_offp[(size_t)ch*BN*18*HWSZ + i];
    g_off[i] = v;
}

// ---------------- BN stats ----------------
__global__ __launch_bounds__(256) void bnstats()
{
    int c = blockIdx.x;
    int tid = threadIdx.x;
    float s = 0.f, s2 = 0.f;
    for (int i = tid; i < BN*HWSZ; i += 256) {
        int b = i / HWSZ, hw = i % HWSZ;
        float v = g_h3[(size_t)(b*128 + c)*HWSZ + hw];
        s += v; s2 += v*v;
    }
    __shared__ float sh[256], sh2[256];
    sh[tid] = s; sh2[tid] = s2;
    __syncthreads();
    for (int o = 128; o > 0; o >>= 1) {
        if (tid < o) { sh[tid] += sh[tid+o]; sh2[tid] += sh2[tid+o]; }
        __syncthreads();
    }
    if (tid == 0) {
        float n = (float)(BN*HWSZ);
        float mean = sh[0]/n;
        float var  = sh2[0]/n - mean*mean;
        g_mean[c] = mean;
        g_rstd[c] = rsqrtf(var + 1e-5f);
    }
}

__global__ __launch_bounds__(256) void bngelu(
    const float* __restrict__ gamma, const float* __restrict__ beta,
    float* __restrict__ out)
{
    int i = blockIdx.x*256 + threadIdx.x;
    if (i >= BN*CC*HWSZ) return;
    int c = (i / HWSZ) & 127;
    float v = g_h3[i];
    v = (v - g_mean[c]) * g_rstd[c] * gamma[c] + beta[c];
    out[i] = 0.5f * v * (1.f + erff(v * 0.70710678118654752440f));
}

// ---------------- mask conv (split-ci) ----------------
__global__ __launch_bounds__(224) void maskconv_part(const float* __restrict__ hsrc)
{
    int x  = threadIdx.x;
    int h  = blockIdx.x*4 + threadIdx.y;
    int b  = blockIdx.y;
    int ch = blockIdx.z;
    int ci0 = ch*32;
    int hw = h*WW + x;

    float acc = 0.f;
    for (int ci = 0; ci < 32; ci++) {
        const float* ip = hsrc + (size_t)(b*128 + ci0 + ci)*HWSZ;
        float r[9];
        #pragma unroll
        for (int dy = 0; dy < 3; dy++) {
            int yy = h + dy - 1;
            bool yok = ((unsigned)yy < HH);
            #pragma unroll
            for (int dx = 0; dx < 3; dx++) {
                int xx = x + dx - 1;
                r[dy*3+dx] = (yok && (unsigned)xx < WW) ? __ldg(ip + yy*WW + xx) : 0.f;
            }
        }
        const float4* wq = (const float4*)(g_maskwt + (size_t)(ci0+ci)*12);
        float4 wa  = __ldg(wq);
        float4 wb4 = __ldg(wq+1);
        float4 wc  = __ldg(wq+2);
        acc += r[0]*wa.x + r[1]*wa.y + r[2]*wa.z
             + r[3]*wa.w + r[4]*wb4.x + r[5]*wb4.y
             + r[6]*wb4.z + r[7]*wb4.w + r[8]*wc.x;
    }
    g_maskp[(size_t)(ch*BN + b)*HWSZ + hw] = acc;
}

__global__ __launch_bounds__(256) void maskconv_reduce(
    const float* __restrict__ bias, float* __restrict__ out)
{
    int i = blockIdx.x*256 + threadIdx.x;
    if (i >= BN*HWSZ) return;
    float v = bias[0];
    #pragma unroll
    for (int ch = 0; ch < 4; ch++)
        v += g_maskp[(size_t)ch*BN*HWSZ + i];
    out[i] = v;
}

// ---------------- launch ----------------
extern "C" void kernel_launch(void* const* d_in, const int* in_sizes, int n_in,
                              void* d_out, int out_size)
{
    const float* x       = (const float*)d_in[0];
    const float* y       = (const float*)d_in[1];
    const float* conv_w  = (const float*)d_in[2];
    const float* conv_b  = (const float*)d_in[3];
    const float* off_w   = (const float*)d_in[4];
    const float* off_b   = (const float*)d_in[5];
    const float* dcn_w   = (const float*)d_in[6];
    const float* dcn_b   = (const float*)d_in[7];
    const float* conv2_w = (const float*)d_in[8];
    const float* conv2_b = (const float*)d_in[9];
    const float* bn_g    = (const float*)d_in[10];
    const float* bn_b    = (const float*)d_in[11];
    const float* mask_w  = (const float*)d_in[12];
    const float* mask_b  = (const float*)d_in[13];
    float* out = (float*)d_out;

    float *p_h1, *p_h2, *p_h3;
    uint8_t *p_w1g, *p_w2g, *p_wdg;
    cudaGetSymbolAddress((void**)&p_h1,  g_h1);
    cudaGetSymbolAddress((void**)&p_h2,  g_h2);
    cudaGetSymbolAddress((void**)&p_h3,  g_h3);
    cudaGetSymbolAddress((void**)&p_w1g, g_w1g);
    cudaGetSymbolAddress((void**)&p_w2g, g_w2g);
    cudaGetSymbolAddress((void**)&p_wdg, g_wdg);

    // weight prep
    prep_wgemm<<<(128*2304 + 255)/256, 256>>>(conv_w,  p_w1g, 256, 0);
    prep_wgemm<<<(128*1152 + 255)/256, 256>>>(conv2_w, p_w2g, 128, 0);
    prep_wgemm<<<(128*1152 + 255)/256, 256>>>(dcn_w,   p_wdg, 128, 1);
    prep_offw<<<(CC*18 + 255)/256, 256>>>(off_w);
    prep_maskw<<<1, 256>>>(mask_w);

    // conv1: fused im2col GEMM over concat(x,y)
    gemm_fused<256, 0><<<dim3(49, BN), 256>>>(x, y, p_w1g, conv_b, p_h1);

    // offset conv 128 -> 18
    offconv_part<<<dim3(14, BN, 4), dim3(56, 4)>>>();
    offconv_reduce<<<(BN*18*HWSZ + 255)/256, 256>>>(off_b);

    // dcn: fused bilinear-gather GEMM
    gemm_fused<128, 2><<<dim3(49, BN), 256>>>(nullptr, nullptr, p_wdg, dcn_b, p_h2);

    // conv2: fused im2col GEMM
    gemm_fused<128, 1><<<dim3(49, BN), 256>>>(p_h2, nullptr, p_w2g, conv2_b, p_h3);

    // batch norm + GELU -> d_out
    bnstats<<<CC, 256>>>();
    bngelu<<<(BN*CC*HWSZ + 255)/256, 256>>>(bn_g, bn_b, out);

    // mask conv -> d_out tail
    maskconv_part<<<dim3(14, BN, 4), dim3(56, 4)>>>(out);
    maskconv_reduce<<<(BN*HWSZ + 255)/256, 256>>>(mask_b, out + (size_t)BN*CC*HWSZ);

    (void)in_sizes; (void)n_in; (void)out_size;
}